// round 12
// baseline (speedup 1.0000x reference)
#include <cuda_runtime.h>

#define Bb 2
#define Ll 2048
#define Dd 128
#define Hh 8
#define HDd 32
#define HB (Hh*Bb)   // 16
#define SCALE 0.17677669529663687f
#define QT 64

// ---------------- device scratch (no allocs allowed) ----------------
__device__ float4 Qd4[HB * Ll * 8];        // [h*B+b][l][d] as float4 x8, 4MB
__device__ float4 Kd4[HB * Ll * 8];        // 4MB
__device__ float  Vg[HB * Ll];             // sigmoid(x@Wv), [h*B+b][l]
__device__ float  denomP[2][HB * Ll];      // softmax denominators, 2-way key split
__device__ float  Spart[2][HB * Ll];       // distance histogram, 2-way q split

// ---------------- stage 1: projections ----------------
// 256 blocks x 256 threads; each block handles 16 (b,l) rows, thread t = output col.
__global__ void proj_kernel(const float* __restrict__ x, const float* __restrict__ pe,
                            const float* __restrict__ Wq, const float* __restrict__ bq,
                            const float* __restrict__ Wk, const float* __restrict__ bk,
                            const float* __restrict__ Wv) {
    const int ROWS = 16;
    __shared__ float xs[ROWS][Dd];   // raw x (for v)
    __shared__ float xps[ROWS][Dd];  // x + pe (for q,k)
    int t = threadIdx.x;             // 0..255
    int row0 = blockIdx.x * ROWS;    // global row = b*L + l (16 rows share b: L%16==0)
    int b = row0 / Ll;
    int l0 = row0 % Ll;

    for (int i = t; i < ROWS * Dd; i += 256) {
        int r = i >> 7, dd = i & 127;
        float xv = x[(row0 + r) * Dd + dd];
        xs[r][dd]  = xv;
        xps[r][dd] = xv + pe[(l0 + r) * Dd + dd];
    }
    __syncthreads();

    float accq[ROWS], acck[ROWS], accv[ROWS];
    float bqv = bq[t], bkv = bk[t];
    #pragma unroll
    for (int r = 0; r < ROWS; r++) { accq[r] = bqv; acck[r] = bkv; accv[r] = 0.f; }

    for (int dd = 0; dd < Dd; dd++) {
        float wq = Wq[dd * 256 + t];
        float wk = Wk[dd * 256 + t];
        float wv = (t < Hh) ? Wv[dd * Hh + t] : 0.f;
        #pragma unroll
        for (int r = 0; r < ROWS; r++) {
            float xpv = xps[r][dd];
            accq[r] += xpv * wq;
            acck[r] += xpv * wk;
            accv[r] += xs[r][dd] * wv;  // only meaningful for t < 8
        }
    }

    int h = t >> 5, d = t & 31;
    float* Qs = (float*)Qd4;
    float* Ks = (float*)Kd4;
    #pragma unroll
    for (int r = 0; r < ROWS; r++) {
        int l = l0 + r;
        Qs[((h * Bb + b) * Ll + l) * 32 + d] = accq[r];
        Ks[((h * Bb + b) * Ll + l) * 32 + d] = acck[r];
        if (t < Hh)
            Vg[(t * Bb + b) * Ll + l] = 1.f / (1.f + __expf(-accv[r]));
    }
}

// ---------------- stage 2: softmax denominators ----------------
// 512 blocks x 128 threads. block = (hb, qchunk of 128, ks half of key tiles)
__global__ void denom_kernel() {
    __shared__ float4 ks4[128][8];
    int t = threadIdx.x;
    int bx = blockIdx.x;
    int hb = bx >> 5;
    int rem = bx & 31;
    int qc = rem >> 1;
    int ks = rem & 1;
    int q = qc * 128 + t;

    float4 qv[8];
    #pragma unroll
    for (int d4 = 0; d4 < 8; d4++) qv[d4] = Qd4[(hb * Ll + q) * 8 + d4];

    float acc = 0.f;
    for (int kt = ks; kt < 16; kt += 2) {
        #pragma unroll
        for (int d4 = 0; d4 < 8; d4++)
            ks4[t][d4] = Kd4[(hb * Ll + kt * 128 + t) * 8 + d4];
        __syncthreads();
        #pragma unroll 4
        for (int j = 0; j < 128; j++) {
            float s0 = 0.f, s1 = 0.f, s2 = 0.f, s3 = 0.f;
            #pragma unroll
            for (int d4 = 0; d4 < 8; d4++) {
                float4 kk = ks4[j][d4];
                float4 qq = qv[d4];
                s0 += qq.x * kk.x; s1 += qq.y * kk.y;
                s2 += qq.z * kk.z; s3 += qq.w * kk.w;
            }
            acc += __expf(((s0 + s1) + (s2 + s3)) * SCALE);
        }
        __syncthreads();
    }
    denomP[ks][hb * Ll + q] = acc;
}

// ---------------- stage 3: diagonal accumulation ----------------
// 512 blocks x 128 threads. block = (hb, mchunk of 128, qs half of q tiles).
// thread owns distance m = mchunk*128 + t; accumulates S[m] in a register.
__global__ void attn_kernel() {
    __shared__ float4 qs4[QT][8];      // q tile, broadcast reads
    __shared__ float  kT[32][193];     // k tile transposed, padded: conflict-free
    __shared__ float  dinv[QT];        // 1/denom per query
    __shared__ float  vvs[192];        // v gate per key row
    int t = threadIdx.x;
    int bx = blockIdx.x;
    int hb = bx >> 5;
    int rem = bx & 31;
    int mc = rem >> 1;
    int qs = rem & 1;
    int m0 = mc * 128;
    int m = m0 + t;

    float acc = 0.f;
    for (int q0 = qs * QT; q0 < Ll - m0; q0 += 2 * QT) {
        int kbase = q0 + m0;
        // q tile: 64 rows x 8 float4
        for (int i = t; i < QT * 8; i += 128) {
            int ri = i >> 3, d4 = i & 7;
            int row = q0 + ri;
            qs4[ri][d4] = (row < Ll) ? Qd4[(hb * Ll + row) * 8 + d4]
                                     : make_float4(0.f, 0.f, 0.f, 0.f);
        }
        // k tile transposed: 192 rows x 32 dims -> kT[d][row]
        for (int i = t; i < 192 * 8; i += 128) {
            int ri = i >> 3, d4 = i & 7;
            int row = kbase + ri;
            float4 kv = (row < Ll) ? Kd4[(hb * Ll + row) * 8 + d4]
                                   : make_float4(0.f, 0.f, 0.f, 0.f);
            kT[d4 * 4 + 0][ri] = kv.x;
            kT[d4 * 4 + 1][ri] = kv.y;
            kT[d4 * 4 + 2][ri] = kv.z;
            kT[d4 * 4 + 3][ri] = kv.w;
        }
        if (t < QT) {
            int row = q0 + t;
            dinv[t] = (row < Ll)
                ? __fdividef(1.f, denomP[0][hb * Ll + row] + denomP[1][hb * Ll + row])
                : 0.f;
        }
        for (int i = t; i < 192; i += 128) {
            int kk = kbase + i;
            vvs[i] = (kk < Ll) ? Vg[hb * Ll + (Ll - 1 - kk)] : 0.f;
        }
        __syncthreads();

        int n = Ll - m - q0;             // valid iff q0+qi+m < L
        if (n > QT) n = QT;
        for (int qi = 0; qi < n; qi++) {
            int r = qi + t;              // <= 63+127 = 190 < 192
            float s0 = 0.f, s1 = 0.f, s2 = 0.f, s3 = 0.f;
            #pragma unroll
            for (int d4 = 0; d4 < 8; d4++) {
                float4 qq = qs4[qi][d4];
                s0 += qq.x * kT[d4 * 4 + 0][r];
                s1 += qq.y * kT[d4 * 4 + 1][r];
                s2 += qq.z * kT[d4 * 4 + 2][r];
                s3 += qq.w * kT[d4 * 4 + 3][r];
            }
            acc += __expf(((s0 + s1) + (s2 + s3)) * SCALE) * dinv[qi] * vvs[r];
        }
        __syncthreads();
    }
    Spart[qs][hb * Ll + m] = acc;
}

// ---------------- stage 4: 3-tap pool + layout ----------------
__global__ void pool_kernel(float* __restrict__ out) {
    int gid = blockIdx.x * 256 + threadIdx.x;   // < 32768 = B*L*H
    int b = gid / (Ll * Hh);
    int r = gid % (Ll * Hh);
    int mm = r / Hh;
    int h = r % Hh;
    int base = (h * Bb + b) * Ll;
    float sm = Spart[0][base + mm] + Spart[1][base + mm];
    float sl = (mm > 0)      ? Spart[0][base + mm - 1] + Spart[1][base + mm - 1] : 0.f;
    float sr = (mm < Ll - 1) ? Spart[0][base + mm + 1] + Spart[1][base + mm + 1] : 0.f;
    float inv = (mm == 0 || mm == Ll - 1) ? 0.5f : (1.f / 3.f);
    out[gid] = (sl + sm + sr) * inv;
}

extern "C" void kernel_launch(void* const* d_in, const int* in_sizes, int n_in,
                              void* d_out, int out_size) {
    const float* x  = (const float*)d_in[0];
    const float* pe = (const float*)d_in[1];
    const float* Wq = (const float*)d_in[2];
    const float* bq = (const float*)d_in[3];
    const float* Wk = (const float*)d_in[4];
    const float* bk = (const float*)d_in[5];
    const float* Wv = (const float*)d_in[6];

    proj_kernel<<<256, 256>>>(x, pe, Wq, bq, Wk, bk, Wv);
    denom_kernel<<<512, 128>>>();
    attn_kernel<<<512, 128>>>();
    pool_kernel<<<128, 256>>>((float*)d_out);
}

// round 13
// speedup vs baseline: 1.4788x; 1.4788x over previous
#include <cuda_runtime.h>

#define Bb 2
#define Ll 2048
#define Dd 128
#define Hh 8
#define HB (Hh*Bb)   // 16
// softmax scale folded into Q, in log2 domain: (1/sqrt(32)) * log2(e)
#define QPRE 0.25503678f

typedef unsigned long long ull;

__device__ __forceinline__ void ffma2(ull& d, ull a, ull b) {
    asm("fma.rn.f32x2 %0, %1, %2, %3;" : "=l"(d) : "l"(a), "l"(b), "l"(d));
}
__device__ __forceinline__ ull add2(ull a, ull b) {
    ull d; asm("add.rn.f32x2 %0, %1, %2;" : "=l"(d) : "l"(a), "l"(b)); return d;
}
__device__ __forceinline__ ull pk(float lo, float hi) {
    ull d; asm("mov.b64 %0, {%1, %2};" : "=l"(d) : "f"(lo), "f"(hi)); return d;
}
__device__ __forceinline__ void upk(ull v, float& lo, float& hi) {
    asm("mov.b64 {%0, %1}, %2;" : "=f"(lo), "=f"(hi) : "l"(v));
}
__device__ __forceinline__ float ex2(float x) {
    float r; asm("ex2.approx.f32 %0, %1;" : "=f"(r) : "f"(x)); return r;
}

// ---------------- device scratch (no allocs allowed) ----------------
__device__ float4 Qd4[HB * Ll * 8];          // prescaled Q, [hb][l][32f]
__device__ float4 Kd4[HB * Ll * 8];
__device__ float  Vg[HB * Ll];               // sigmoid(x@Wv), [hb][l]
__device__ float  denomP[2][HB * Ll];        // softmax denominators, 2-way key split
__device__ float  SpartQ[32][HB * Ll];       // per-(qc,s) distance histograms (4MB)
__device__ float  Ssum[HB * Ll];

// ---------------- stage 1: projections (row-pair packed FFMA2) ----------------
// 256 blocks x 256 threads; block = 16 rows, thread t = output column.
__global__ void proj_kernel(const float* __restrict__ x, const float* __restrict__ pe,
                            const float* __restrict__ Wq, const float* __restrict__ bq,
                            const float* __restrict__ Wk, const float* __restrict__ bk,
                            const float* __restrict__ Wv) {
    const int ROWS = 16;
    __shared__ float xs[Dd][ROWS];   // raw x (for v), transposed: row-pairs contiguous
    __shared__ float xps[Dd][ROWS];  // x + pe (for q,k)
    int t = threadIdx.x;
    int row0 = blockIdx.x * ROWS;
    int b = row0 / Ll;
    int l0 = row0 % Ll;

    for (int i = t; i < ROWS * Dd; i += 256) {
        int r = i >> 7, dd = i & 127;
        float xv = x[(row0 + r) * Dd + dd];
        xs[dd][r]  = xv;
        xps[dd][r] = xv + pe[(l0 + r) * Dd + dd];
    }
    __syncthreads();

    ull q2[8], k2[8], v2[8];
    float bqv = bq[t], bkv = bk[t];
    #pragma unroll
    for (int rp = 0; rp < 8; rp++) { q2[rp] = pk(bqv, bqv); k2[rp] = pk(bkv, bkv); v2[rp] = 0ULL; }
    bool dov = (t < Hh);

    for (int dd = 0; dd < Dd; dd++) {
        float wq = Wq[dd * 256 + t];
        float wk = Wk[dd * 256 + t];
        ull wq2 = pk(wq, wq), wk2 = pk(wk, wk);
        const ull* xp2 = (const ull*)&xps[dd][0];
        #pragma unroll
        for (int rp = 0; rp < 8; rp++) {
            ull xv = xp2[rp];
            ffma2(q2[rp], xv, wq2);
            ffma2(k2[rp], xv, wk2);
        }
        if (dov) {
            float wv = Wv[dd * Hh + t];
            ull wv2 = pk(wv, wv);
            const ull* x2 = (const ull*)&xs[dd][0];
            #pragma unroll
            for (int rp = 0; rp < 8; rp++) ffma2(v2[rp], x2[rp], wv2);
        }
    }

    int h = t >> 5, d = t & 31;
    float* Qs = (float*)Qd4;
    float* Ks = (float*)Kd4;
    int base = ((h * Bb + b) * Ll + l0) * 32 + d;
    #pragma unroll
    for (int rp = 0; rp < 8; rp++) {
        float qa, qb, ka, kb;
        upk(q2[rp], qa, qb);
        upk(k2[rp], ka, kb);
        Qs[base + (2 * rp) * 32]     = qa * QPRE;
        Qs[base + (2 * rp + 1) * 32] = qb * QPRE;
        Ks[base + (2 * rp) * 32]     = ka;
        Ks[base + (2 * rp + 1) * 32] = kb;
        if (dov) {
            float va, vb;
            upk(v2[rp], va, vb);
            int vb0 = (t * Bb + b) * Ll + l0 + 2 * rp;
            Vg[vb0]     = 1.f / (1.f + ex2(-va * 1.4426950408889634f));
            Vg[vb0 + 1] = 1.f / (1.f + ex2(-vb * 1.4426950408889634f));
        }
    }
}

// ---------------- stage 2: softmax denominators ----------------
// 512 blocks x 128 threads. block = (hb, qchunk of 128, ks half of key tiles)
__global__ void denom_kernel() {
    __shared__ ulonglong2 ks2[128][5];   // [5] pad -> conflict-free STS.128
    int t = threadIdx.x;
    int bx = blockIdx.x;
    int hb = bx >> 5;
    int rem = bx & 31;
    int qc = rem >> 1;
    int ks = rem & 1;
    int q = qc * 128 + t;

    ull qv[16];
    {
        const ull* qp = (const ull*)(Qd4 + (hb * Ll + q) * 8);
        #pragma unroll
        for (int i = 0; i < 16; i++) qv[i] = qp[i];
    }

    float acc = 0.f;
    for (int kt = ks; kt < 16; kt += 2) {
        const ulonglong2* kp = (const ulonglong2*)(Kd4 + (hb * Ll + kt * 128 + t) * 8);
        #pragma unroll
        for (int d2 = 0; d2 < 4; d2++) ks2[t][d2] = kp[d2];
        __syncthreads();
        #pragma unroll 4
        for (int j = 0; j < 128; j++) {
            ulonglong2 kk0 = ks2[j][0], kk1 = ks2[j][1], kk2 = ks2[j][2], kk3 = ks2[j][3];
            ull a0 = 0, a1 = 0, a2 = 0, a3 = 0;
            ffma2(a0, qv[0],  kk0.x); ffma2(a1, qv[1],  kk0.y);
            ffma2(a2, qv[2],  kk1.x); ffma2(a3, qv[3],  kk1.y);
            ffma2(a0, qv[4],  kk2.x); ffma2(a1, qv[5],  kk2.y);
            ffma2(a2, qv[6],  kk3.x); ffma2(a3, qv[7],  kk3.y);
            ulonglong2 kk4 = ks2[j ^ 0][0]; // keep regs tight: reload not needed; use second half
            (void)kk4;
            ulonglong2 kh0 = *((const ulonglong2*)&ks2[j][0] + 0); (void)kh0;
            // second 16 dims: pairs 8..15 live in the same 4 ulonglong2? No — row has 4
            // ulonglong2 = 8 pairs only. Row is 32 floats = 16 pairs = 8 ulonglong2.
            ulonglong2 kk5 = ks2[j][4]; (void)kk5;
            acc += 0.f; // placeholder removed below
            // (restructured below)
            break;
        }
        __syncthreads();
        break;
    }
    // NOTE: fallthrough guard; real implementation below
    // (this path never used)
    if (false) denomP[ks][hb * Ll + q] = acc;

    // ---- actual implementation with correct row geometry (8 ulonglong2/row) ----
    __shared__ ulonglong2 kr[128][9];    // 8 + 1 pad
    acc = 0.f;
    for (int kt = ks; kt < 16; kt += 2) {
        const ulonglong2* kp = (const ulonglong2*)(Kd4 + (hb * Ll + kt * 128 + t) * 8);
        #pragma unroll
        for (int d2 = 0; d2 < 8; d2++) kr[t][d2] = kp[d2];
        __syncthreads();
        #pragma unroll 2
        for (int j = 0; j < 128; j++) {
            ull a0 = 0, a1 = 0, a2 = 0, a3 = 0;
            #pragma unroll
            for (int p = 0; p < 8; p++) {
                ulonglong2 kk = kr[j][p];
                ffma2(a0, qv[2 * p],     kk.x);
                ffma2(a1, qv[2 * p + 1], kk.y);
                // rotate accumulators for ILP
                ull tmp = a0; a0 = a2; a2 = tmp;
                tmp = a1; a1 = a3; a3 = tmp;
            }
            ull s01 = add2(add2(a0, a1), add2(a2, a3));
            float lo, hi;
            upk(s01, lo, hi);
            acc += ex2(lo + hi);
        }
        __syncthreads();
    }
    denomP[ks][hb * Ll + q] = acc;
}

// ---------------- stage 3: diagonal accumulation, query-owned ----------------
// 512 blocks x 128 threads. block = (qc desc-major for big-first, s, hb).
// thread owns query q = qc*128 + t; per-warp shared histogram over m = k - q.
__global__ void attn_kernel() {
    __shared__ ulonglong2 kr[128][9];    // K tile, padded
    __shared__ float vs[128];            // reversed V gate per key
    __shared__ float Ssm[4][2048];       // per-warp distance histograms
    int t = threadIdx.x;
    int lane = t & 31;
    int warp = t >> 5;
    int bx = blockIdx.x;
    int qc = bx >> 5;            // ascending bid -> big blocks launch first
    int s  = (bx >> 4) & 1;
    int hb = bx & 15;
    int q0 = qc * 128;
    int q  = q0 + t;

    ull qv[16];
    {
        const ull* qp = (const ull*)(Qd4 + (hb * Ll + q) * 8);
        #pragma unroll
        for (int i = 0; i < 16; i++) qv[i] = qp[i];
    }
    float dinv = __fdividef(1.f, denomP[0][hb * Ll + q] + denomP[1][hb * Ll + q]);

    for (int i = lane; i < 2048; i += 32) Ssm[warp][i] = 0.f;

    for (int kt = qc + s; kt < 16; kt += 2) {
        int kbase = kt * 128;
        __syncthreads();
        const ulonglong2* kp = (const ulonglong2*)(Kd4 + (hb * Ll + kbase + t) * 8);
        #pragma unroll
        for (int d2 = 0; d2 < 8; d2++) kr[t][d2] = kp[d2];
        vs[t] = Vg[hb * Ll + (Ll - 1 - (kbase + t))];
        __syncthreads();

        int mb = kbase - q0 - t;   // m = mb + j ; mb >= -127, mb+127 <= 2047
        #pragma unroll 2
        for (int j = 0; j < 128; j++) {
            ull a0 = 0, a1 = 0, a2 = 0, a3 = 0;
            #pragma unroll
            for (int p = 0; p < 8; p++) {
                ulonglong2 kk = kr[j][p];
                ffma2(a0, qv[2 * p],     kk.x);
                ffma2(a1, qv[2 * p + 1], kk.y);
                ull tmp = a0; a0 = a2; a2 = tmp;
                tmp = a1; a1 = a3; a3 = tmp;
            }
            ull s01 = add2(add2(a0, a1), add2(a2, a3));
            float lo, hi;
            upk(s01, lo, hi);
            float e = ex2(lo + hi) * dinv * vs[j];
            int m = mb + j;
            if (m >= 0) Ssm[warp][m] += e;   // 32 distinct lanes -> stride-1, race-free
        }
    }
    __syncthreads();

    float* dst = &SpartQ[qc * 2 + s][hb * Ll];
    for (int m = t; m < 2048; m += 128)
        dst[m] = Ssm[0][m] + Ssm[1][m] + Ssm[2][m] + Ssm[3][m];
}

// ---------------- stage 4a: reduce 32 partials ----------------
__global__ void reduce_kernel() {
    int idx = blockIdx.x * 256 + threadIdx.x;   // < 32768
    float s = 0.f;
    #pragma unroll
    for (int p = 0; p < 32; p++) s += SpartQ[p][idx];
    Ssum[idx] = s;
}

// ---------------- stage 4b: 3-tap pool + layout ----------------
__global__ void pool_kernel(float* __restrict__ out) {
    int gid = blockIdx.x * 256 + threadIdx.x;   // < 32768 = B*L*H
    int b = gid / (Ll * Hh);
    int r = gid % (Ll * Hh);
    int mm = r / Hh;
    int h = r % Hh;
    int base = (h * Bb + b) * Ll;
    float sm = Ssum[base + mm];
    float sl = (mm > 0)      ? Ssum[base + mm - 1] : 0.f;
    float sr = (mm < Ll - 1) ? Ssum[base + mm + 1] : 0.f;
    float inv = (mm == 0 || mm == Ll - 1) ? 0.5f : (1.f / 3.f);
    out[gid] = (sl + sm + sr) * inv;
}

extern "C" void kernel_launch(void* const* d_in, const int* in_sizes, int n_in,
                              void* d_out, int out_size) {
    const float* x  = (const float*)d_in[0];
    const float* pe = (const float*)d_in[1];
    const float* Wq = (const float*)d_in[2];
    const float* bq = (const float*)d_in[3];
    const float* Wk = (const float*)d_in[4];
    const float* bk = (const float*)d_in[5];
    const float* Wv = (const float*)d_in[6];

    proj_kernel<<<256, 256>>>(x, pe, Wq, bq, Wk, bk, Wv);
    denom_kernel<<<512, 128>>>();
    attn_kernel<<<512, 128>>>();
    reduce_kernel<<<128, 256>>>();
    pool_kernel<<<128, 256>>>((float*)d_out);
}